// round 5
// baseline (speedup 1.0000x reference)
#include <cuda_runtime.h>
#include <math.h>

// Problem constants
#define SQ  3072   // sequence length
#define DD  512    // model dim = H*DK = H*DV
#define HH  8      // heads
#define DKV 64     // head dim

#define RPC 16                         // query rows per fused CTA
#define PSTRIDE 3076                   // padded P row stride (floats); mod 32 = 4
#define SMEM_FUSED (RPC * PSTRIDE * 4 + 64 * 64 * 4)   // 196864 + 16384 = 213248

typedef unsigned long long ull;

// Scratch (device globals; no allocation allowed)
__device__ float g_q[SQ * DD];
__device__ float g_k[SQ * DD];
__device__ float g_v[SQ * DD];
__device__ float g_o[SQ * DD];
__device__ float g_pre[SQ * DD];

// ---------------------------------------------------------------------------
// Packed fp32x2 FMA (Blackwell sm_10x; 2 FMAs per instruction on fma pipe)
// ---------------------------------------------------------------------------
__device__ __forceinline__ void fma2(ull& d, ull a, ull b) {
    asm("fma.rn.f32x2 %0, %1, %2, %0;" : "+l"(d) : "l"(a), "l"(b));
}

__device__ __forceinline__ ull dup2(float v) {
    union { float2 f; ull u; } c;
    c.f = make_float2(v, v);
    return c.u;
}

// ---------------------------------------------------------------------------
// Shared-tile consumer: BK=16, 4 row-pairs per thread, 2*NJP columns/thread.
// Ast: k-major [16][132] floats (Ast[k][row]); thread's rows = ty*8..ty*8+7.
// Bsd: ulonglong2 entries [16][NJP][17]; entry (k,jp,tx) holds the duplicated
//      pairs (b,b) for columns tx*2NJP + 2jp and tx*2NJP + 2jp + 1 of the
//      k-th K-slice. 17-entry pad (272B row) keeps tx-stride 16B conflict-free.
// accp[ip][j] packs output rows (ty*8+2ip, ty*8+2ip+1) at column j.
// ---------------------------------------------------------------------------
template<int NJP>
__device__ __forceinline__ void consume16(const float* __restrict__ Ast,
                                          const ulonglong2* __restrict__ Bsd,
                                          ull accp[4][2 * NJP], int ty, int tx)
{
#pragma unroll
    for (int kk = 0; kk < 16; kk++) {
        ulonglong2 u0 = *(const ulonglong2*)(Ast + kk * 132 + ty * 8);
        ulonglong2 u1 = *(const ulonglong2*)(Ast + kk * 132 + ty * 8 + 4);
        ull ap0 = u0.x, ap1 = u0.y, ap2 = u1.x, ap3 = u1.y;
        const ulonglong2* bp = Bsd + kk * NJP * 17 + tx;
#pragma unroll
        for (int jp = 0; jp < NJP; jp++) {
            ulonglong2 bb = bp[jp * 17];
            fma2(accp[0][2 * jp], ap0, bb.x);
            fma2(accp[1][2 * jp], ap1, bb.x);
            fma2(accp[2][2 * jp], ap2, bb.x);
            fma2(accp[3][2 * jp], ap3, bb.x);
            fma2(accp[0][2 * jp + 1], ap0, bb.y);
            fma2(accp[1][2 * jp + 1], ap1, bb.y);
            fma2(accp[2][2 * jp + 1], ap2, bb.y);
            fma2(accp[3][2 * jp + 1], ap3, bb.y);
        }
    }
}

// ---------------------------------------------------------------------------
// 128x128-tile GEMM: C = (A@B + bias)*scale (+ resid). K=512, N=512 fixed.
// A row-major lda=512, B row-major ldb=512, C ldc=512. 256 threads.
// Software-pipelined: next k-chunk's LDGs issue right after the barrier that
// publishes the current chunk, overlapping load latency with consume16.
// ---------------------------------------------------------------------------
__device__ __forceinline__ void gemm128_body(
    const float* __restrict__ A, const float* __restrict__ B,
    const float* __restrict__ bias, const float* __restrict__ resid,
    float* __restrict__ C, float scale, int bx, int by)
{
    __shared__ __align__(16) float Ast[16 * 132];
    __shared__ __align__(16) ulonglong2 Bsd[16 * 4 * 17];

    const int tid = threadIdx.x;
    const int ty = tid >> 4, tx = tid & 15;
    const int arow = tid >> 1, acol = (tid & 1) * 8;
    const int brow = tid >> 4;

    ull accp[4][8];
#pragma unroll
    for (int i = 0; i < 4; i++)
#pragma unroll
        for (int j = 0; j < 8; j++) accp[i][j] = 0ull;

    const float* Ap = A + (size_t)(by * 128 + arow) * 512 + acol;
    const float* Bp = B + (size_t)brow * 512 + bx * 128 + tx * 8;

    float4 a0 = *(const float4*)(Ap);
    float4 a1 = *(const float4*)(Ap + 4);
    float4 b0 = *(const float4*)(Bp);
    float4 b1 = *(const float4*)(Bp + 4);

    for (int k0 = 0; k0 < 512; k0 += 16) {
        Ast[(acol + 0) * 132 + arow] = a0.x;
        Ast[(acol + 1) * 132 + arow] = a0.y;
        Ast[(acol + 2) * 132 + arow] = a0.z;
        Ast[(acol + 3) * 132 + arow] = a0.w;
        Ast[(acol + 4) * 132 + arow] = a1.x;
        Ast[(acol + 5) * 132 + arow] = a1.y;
        Ast[(acol + 6) * 132 + arow] = a1.z;
        Ast[(acol + 7) * 132 + arow] = a1.w;
        Bsd[(brow * 4 + 0) * 17 + tx] = make_ulonglong2(dup2(b0.x), dup2(b0.y));
        Bsd[(brow * 4 + 1) * 17 + tx] = make_ulonglong2(dup2(b0.z), dup2(b0.w));
        Bsd[(brow * 4 + 2) * 17 + tx] = make_ulonglong2(dup2(b1.x), dup2(b1.y));
        Bsd[(brow * 4 + 3) * 17 + tx] = make_ulonglong2(dup2(b1.z), dup2(b1.w));
        __syncthreads();
        if (k0 + 16 < 512) {           // prefetch next chunk during consume
            a0 = *(const float4*)(Ap + k0 + 16);
            a1 = *(const float4*)(Ap + k0 + 20);
            b0 = *(const float4*)(Bp + (size_t)(k0 + 16) * 512);
            b1 = *(const float4*)(Bp + (size_t)(k0 + 16) * 512 + 4);
        }
        consume16<4>(Ast, Bsd, accp, ty, tx);
        __syncthreads();
    }

#pragma unroll
    for (int ip = 0; ip < 4; ip++) {
        float2 f[8];
#pragma unroll
        for (int j = 0; j < 8; j++) f[j] = *(float2*)&accp[ip][j];
#pragma unroll
        for (int l = 0; l < 2; l++) {
            size_t row = (size_t)(by * 128 + ty * 8 + ip * 2 + l);
            int col = bx * 128 + tx * 8;
            float v[8];
#pragma unroll
            for (int j = 0; j < 8; j++) v[j] = l ? f[j].y : f[j].x;
            float4 r0, r1;
            r0.x = (v[0] + bias[col + 0]) * scale;
            r0.y = (v[1] + bias[col + 1]) * scale;
            r0.z = (v[2] + bias[col + 2]) * scale;
            r0.w = (v[3] + bias[col + 3]) * scale;
            r1.x = (v[4] + bias[col + 4]) * scale;
            r1.y = (v[5] + bias[col + 5]) * scale;
            r1.z = (v[6] + bias[col + 6]) * scale;
            r1.w = (v[7] + bias[col + 7]) * scale;
            if (resid) {
                float4 e0 = *(const float4*)(resid + row * 512 + col);
                float4 e1 = *(const float4*)(resid + row * 512 + col + 4);
                r0.x += e0.x; r0.y += e0.y; r0.z += e0.z; r0.w += e0.w;
                r1.x += e1.x; r1.y += e1.y; r1.z += e1.z; r1.w += e1.w;
            }
            *(float4*)(C + row * 512 + col)     = r0;
            *(float4*)(C + row * 512 + col + 4) = r1;
        }
    }
}

// ---------------------------------------------------------------------------
// Kernel 1: QKV projections (z selects q/k/v). q pre-scaled by 1/sqrt(dk).
// grid (4, 24, 3), 256 threads
// ---------------------------------------------------------------------------
__global__ void __launch_bounds__(256) qkv_kernel(
    const float* __restrict__ x,
    const float* __restrict__ Wq, const float* __restrict__ bq,
    const float* __restrict__ Wk, const float* __restrict__ bk,
    const float* __restrict__ Wv, const float* __restrict__ bv)
{
    const int z = blockIdx.z;
    const float* B    = (z == 0) ? Wq : ((z == 1) ? Wk : Wv);
    const float* bias = (z == 0) ? bq : ((z == 1) ? bk : bv);
    float* C          = (z == 0) ? g_q : ((z == 1) ? g_k : g_v);
    const float scale = (z == 0) ? 0.125f : 1.0f;   // 1/sqrt(64)
    gemm128_body(x, B, bias, nullptr, C, scale, blockIdx.x, blockIdx.y);
}

// ---------------------------------------------------------------------------
// Kernel 2: logits[h] = q_h @ k_h^T. Tile 128x128, K=64 (4 chunks of 16).
// grid (24, 24, 8), 256 threads. B matrix = K^T: column index = key row.
// Writer thread owns ONE key row (jrow) and 8 d-values; it writes 8-byte
// duplicated-pair halves: entry (d, jp=jlo>>1, tx=jhi), half = jlo&1,
// where jlo=jrow&7, jhi=jrow>>3 (consumer column = tx*8 + 2jp + half = jrow).
// Software-pipelined like gemm128_body.
// ---------------------------------------------------------------------------
__global__ void __launch_bounds__(256) qk_kernel(float* __restrict__ attn)
{
    const int h = blockIdx.z;
    const int bx = blockIdx.x, by = blockIdx.y;
    __shared__ __align__(16) float Qst[16 * 132];
    __shared__ __align__(16) ulonglong2 Ksd[16 * 4 * 17];

    const int tid = threadIdx.x;
    const int ty = tid >> 4, tx = tid & 15;
    const int arow = tid >> 1, acol = (tid & 1) * 8;   // Q loader
    const int jrow = tid >> 1, dcol = (tid & 1) * 8;   // K loader

    ull accp[4][8];
#pragma unroll
    for (int i = 0; i < 4; i++)
#pragma unroll
        for (int j = 0; j < 8; j++) accp[i][j] = 0ull;

    const float* qp = g_q + (size_t)(by * 128 + arow) * DD + h * 64 + acol;
    const float* kp = g_k + (size_t)(bx * 128 + jrow) * DD + h * 64 + dcol;
    ull* kd = (ull*)Ksd;
    const int jlo = jrow & 7, jhi = jrow >> 3;
    const int jp = jlo >> 1, half = jlo & 1;

    float4 q0 = *(const float4*)(qp);
    float4 q1 = *(const float4*)(qp + 4);
    float4 k0 = *(const float4*)(kp);
    float4 k1 = *(const float4*)(kp + 4);

#pragma unroll
    for (int c = 0; c < 4; c++) {
        Qst[(acol + 0) * 132 + arow] = q0.x;
        Qst[(acol + 1) * 132 + arow] = q0.y;
        Qst[(acol + 2) * 132 + arow] = q0.z;
        Qst[(acol + 3) * 132 + arow] = q0.w;
        Qst[(acol + 4) * 132 + arow] = q1.x;
        Qst[(acol + 5) * 132 + arow] = q1.y;
        Qst[(acol + 6) * 132 + arow] = q1.z;
        Qst[(acol + 7) * 132 + arow] = q1.w;
        kd[(((dcol + 0) * 4 + jp) * 17 + jhi) * 2 + half] = dup2(k0.x);
        kd[(((dcol + 1) * 4 + jp) * 17 + jhi) * 2 + half] = dup2(k0.y);
        kd[(((dcol + 2) * 4 + jp) * 17 + jhi) * 2 + half] = dup2(k0.z);
        kd[(((dcol + 3) * 4 + jp) * 17 + jhi) * 2 + half] = dup2(k0.w);
        kd[(((dcol + 4) * 4 + jp) * 17 + jhi) * 2 + half] = dup2(k1.x);
        kd[(((dcol + 5) * 4 + jp) * 17 + jhi) * 2 + half] = dup2(k1.y);
        kd[(((dcol + 6) * 4 + jp) * 17 + jhi) * 2 + half] = dup2(k1.z);
        kd[(((dcol + 7) * 4 + jp) * 17 + jhi) * 2 + half] = dup2(k1.w);
        __syncthreads();
        if (c < 3) {                   // prefetch next chunk during consume
            q0 = *(const float4*)(qp + (c + 1) * 16);
            q1 = *(const float4*)(qp + (c + 1) * 16 + 4);
            k0 = *(const float4*)(kp + (c + 1) * 16);
            k1 = *(const float4*)(kp + (c + 1) * 16 + 4);
        }
        consume16<4>(Qst, Ksd, accp, ty, tx);
        __syncthreads();
    }

    float* dst = attn + (size_t)h * SQ * SQ;
#pragma unroll
    for (int ip = 0; ip < 4; ip++) {
        float2 f[8];
#pragma unroll
        for (int j = 0; j < 8; j++) f[j] = *(float2*)&accp[ip][j];
#pragma unroll
        for (int l = 0; l < 2; l++) {
            size_t row = (size_t)(by * 128 + ty * 8 + ip * 2 + l);
            int col = bx * 128 + tx * 8;
            float4 r0, r1;
            r0.x = l ? f[0].y : f[0].x;  r0.y = l ? f[1].y : f[1].x;
            r0.z = l ? f[2].y : f[2].x;  r0.w = l ? f[3].y : f[3].x;
            r1.x = l ? f[4].y : f[4].x;  r1.y = l ? f[5].y : f[5].x;
            r1.z = l ? f[6].y : f[6].x;  r1.w = l ? f[7].y : f[7].x;
            *(float4*)(dst + row * SQ + col)     = r0;
            *(float4*)(dst + row * SQ + col + 4) = r1;
        }
    }
}

// ---------------------------------------------------------------------------
// Kernel 3 (FUSED): entmax-1.5 + (attn @ v) for a 16-row x 1-head tile.
// grid (192, 8), 256 threads, 213248 B dynamic smem (1 CTA/SM).
//
// Phase 1: load logits tile [16][3072] (contiguous in global) into smem P
//          (row stride padded to 3076 floats: mod-32 = 4 -> <=2-way banks
//          for the AV row-pair reads; 16B alignment preserved).
// Phase 2: entmax per row; 16 threads per row (same warp half), butterfly
//          reductions. tau solves sum(max(0,(v-m)/2 - tau))^2 = 1 by Newton
//          from the closed-form full-support init (monotone from below;
//          8 fixed iterations, no divergent early-exit). Writes p to global
//          attn AND back into smem P.
// Phase 3: o[16][64] = P @ V_head. Thread = (co: 16-col group of 4,
//          rp: row-pair of 8, ks: 8-way k-split). V streamed in 64-row
//          (16 KB) smem chunks, register-prefetched one chunk ahead (1 CTA/SM
//          means no cross-CTA latency hiding; prefetch is load-bearing here).
//          f32x2 FMAs: a = dup2(p), b = V col-pairs. Cross-ks reduction via
//          log-rounds reusing the V buffer.
// ---------------------------------------------------------------------------
__global__ void __launch_bounds__(256) entmax_av_kernel(float* __restrict__ attn)
{
    extern __shared__ __align__(16) char sm_[];
    float* P  = (float*)sm_;                 // [RPC][PSTRIDE]
    float* Vs = P + RPC * PSTRIDE;           // [64][64]
    ull*   scratch = (ull*)Vs;               // 2048 ull, reused after AV loop

    const int tid = threadIdx.x;
    const int h = blockIdx.y;
    const int row0 = blockIdx.x * RPC;

    float* gP = attn + (size_t)h * SQ * SQ + (size_t)row0 * SQ; // 16*3072 contiguous

    // ---- Phase 1: stage logits tile ----
    {
        const float4* src = (const float4*)gP;
#pragma unroll
        for (int j = 0; j < 48; j++) {
            int f4 = tid + j * 256;          // 0..12287
            int row = f4 / 768;              // 768 float4 per row
            int k4  = f4 - row * 768;
            *(float4*)(P + row * PSTRIDE + k4 * 4) = src[f4];
        }
    }
    __syncthreads();

    // ---- Phase 2: entmax (16 threads per row) ----
    const int r   = tid >> 4;     // row 0..15
    const int l16 = tid & 15;
    const float4* rowp = (const float4*)(P + r * PSTRIDE);

    // row max
    float m = -1e30f;
#pragma unroll
    for (int j = 0; j < 48; j++) {
        float4 v = rowp[l16 + 16 * j];
        m = fmaxf(m, fmaxf(fmaxf(v.x, v.y), fmaxf(v.z, v.w)));
    }
#pragma unroll
    for (int o = 8; o > 0; o >>= 1) m = fmaxf(m, __shfl_xor_sync(0xffffffffu, m, o));

    // closed-form full-support init on x = (v - m)/2
    float s1 = 0.0f, s2 = 0.0f;
#pragma unroll
    for (int j = 0; j < 48; j++) {
        float4 v = rowp[l16 + 16 * j];
        float x0 = (v.x - m) * 0.5f, x1 = (v.y - m) * 0.5f;
        float x2 = (v.z - m) * 0.5f, x3 = (v.w - m) * 0.5f;
        s1 += (x0 + x1) + (x2 + x3);
        s2 = fmaf(x0, x0, s2); s2 = fmaf(x1, x1, s2);
        s2 = fmaf(x2, x2, s2); s2 = fmaf(x3, x3, s2);
    }
#pragma unroll
    for (int o = 8; o > 0; o >>= 1) {
        s1 += __shfl_xor_sync(0xffffffffu, s1, o);
        s2 += __shfl_xor_sync(0xffffffffu, s2, o);
    }
    const float invn = 1.0f / (float)SQ;
    float mean = s1 * invn;
    float var  = s2 * invn - mean * mean;
    float delta = fmaxf((1.0f - (float)SQ * var) * invn, 0.0f);
    float tau = fminf(mean - sqrtf(delta), -1e-12f);

    // 8 Newton iterations (monotone from below; all 16 lanes of a row agree)
#pragma unroll
    for (int it = 0; it < 8; it++) {
        float cc = 0.5f * m + tau;    // u = 0.5*v - cc
        float a = 0.0f, b = 0.0f;
#pragma unroll
        for (int j = 0; j < 48; j++) {
            float4 v = rowp[l16 + 16 * j];
            float u0 = fmaxf(fmaf(0.5f, v.x, -cc), 0.0f);
            float u1 = fmaxf(fmaf(0.5f, v.y, -cc), 0.0f);
            float u2 = fmaxf(fmaf(0.5f, v.z, -cc), 0.0f);
            float u3 = fmaxf(fmaf(0.5f, v.w, -cc), 0.0f);
            a += (u0 + u1) + (u2 + u3);
            b = fmaf(u0, u0, b); b = fmaf(u1, u1, b);
            b = fmaf(u2, u2, b); b = fmaf(u3, u3, b);
        }
#pragma unroll
        for (int o = 8; o > 0; o >>= 1) {
            a += __shfl_xor_sync(0xffffffffu, a, o);
            b += __shfl_xor_sync(0xffffffffu, b, o);
        }
        if (a > 0.0f) tau += (b - 1.0f) / (2.0f * a);
    }

    // finalize p, write to global AND back to smem
    {
        float cc = 0.5f * m + tau;
        float4* wsm = (float4*)(P + r * PSTRIDE);
        float4* wgl = (float4*)(gP + (size_t)r * SQ);
#pragma unroll
        for (int j = 0; j < 48; j++) {
            float4 v = wsm[l16 + 16 * j];
            float4 p;
            float u;
            u = fmaxf(fmaf(0.5f, v.x, -cc), 0.0f); p.x = u * u;
            u = fmaxf(fmaf(0.5f, v.y, -cc), 0.0f); p.y = u * u;
            u = fmaxf(fmaf(0.5f, v.z, -cc), 0.0f); p.z = u * u;
            u = fmaxf(fmaf(0.5f, v.w, -cc), 0.0f); p.w = u * u;
            wsm[l16 + 16 * j] = p;
            wgl[l16 + 16 * j] = p;
        }
    }
    __syncthreads();

    // ---- Phase 3: AV from smem (V register-prefetched one chunk ahead) ----
    const int co = tid & 3;           // 16-col group
    const int rp = (tid >> 2) & 7;    // row pair
    const int ks = tid >> 5;          // 0..7 (constant per warp)

    ull acc[2][8];
#pragma unroll
    for (int l = 0; l < 2; l++)
#pragma unroll
        for (int q = 0; q < 8; q++) acc[l][q] = 0ull;

    const float* p0base = P + (2 * rp) * PSTRIDE;
    const float* p1base = P + (2 * rp + 1) * PSTRIDE;

    const int vkr = tid >> 4;               // loader: V row within chunk (per j)
    const int vc4 = (tid & 15) * 4;         // loader: V col
    const float* vsrc = g_v + (size_t)vkr * DD + h * 64 + vc4;

    float4 vreg[4];
#pragma unroll
    for (int j = 0; j < 4; j++)
        vreg[j] = *(const float4*)(vsrc + (size_t)(j * 16) * DD);

    for (int kc = 0; kc < SQ; kc += 64) {
        // publish current chunk [64][64]
#pragma unroll
        for (int j = 0; j < 4; j++)
            *(float4*)(Vs + (j * 16 + vkr) * 64 + vc4) = vreg[j];
        __syncthreads();
        if (kc + 64 < SQ) {           // prefetch next chunk during compute
#pragma unroll
            for (int j = 0; j < 4; j++)
                vreg[j] = *(const float4*)(vsrc + (size_t)(kc + 64 + j * 16) * DD);
        }
#pragma unroll
        for (int kk = 0; kk < 8; kk++) {
            int kl = ks * 8 + kk;            // 0..63
            float p0 = p0base[kc + kl];
            float p1 = p1base[kc + kl];
            ull a0 = dup2(p0), a1 = dup2(p1);
            const ulonglong2* vv = (const ulonglong2*)(Vs + kl * 64 + co * 16);
#pragma unroll
            for (int q2 = 0; q2 < 4; q2++) {
                ulonglong2 b = vv[q2];
                fma2(acc[0][2 * q2],     a0, b.x);
                fma2(acc[1][2 * q2],     a1, b.x);
                fma2(acc[0][2 * q2 + 1], a0, b.y);
                fma2(acc[1][2 * q2 + 1], a1, b.y);
            }
        }
        __syncthreads();
    }

    // cross-ks reduction (3 log-rounds, reusing Vs as scratch)
    for (int hlf = 4; hlf >= 1; hlf >>= 1) {
        if (ks >= hlf && ks < 2 * hlf) {
            ull* d = scratch + (size_t)(tid - hlf * 32) * 16;
#pragma unroll
            for (int q = 0; q < 8; q++) { d[q] = acc[0][q]; d[q + 8] = acc[1][q]; }
        }
        __syncthreads();
        if (ks < hlf) {
            const ull* s = scratch + (size_t)tid * 16;
#pragma unroll
            for (int q = 0; q < 8; q++) {
                float2 f0 = *(float2*)&acc[0][q];
                float2 g0 = *(const float2*)&s[q];
                f0.x += g0.x; f0.y += g0.y;
                acc[0][q] = *(ull*)&f0;
                float2 f1 = *(float2*)&acc[1][q];
                float2 g1 = *(const float2*)&s[q + 8];
                f1.x += g1.x; f1.y += g1.y;
                acc[1][q] = *(ull*)&f1;
            }
        }
        __syncthreads();
    }

    // write o tile (threads with ks == 0, i.e. tid < 32)
    if (tid < 32) {
#pragma unroll
        for (int l = 0; l < 2; l++) {
            size_t row = (size_t)(row0 + 2 * rp + l);
            float* op = g_o + row * DD + h * 64 + co * 16;
#pragma unroll
            for (int q2 = 0; q2 < 4; q2++) {
                float2 e0 = *(float2*)&acc[l][2 * q2];
                float2 e1 = *(float2*)&acc[l][2 * q2 + 1];
                float4 w;
                w.x = e0.x; w.y = e0.y; w.z = e1.x; w.w = e1.y;
                *(float4*)(op + q2 * 4) = w;
            }
        }
    }
}

// ---------------------------------------------------------------------------
// Kernel 4: pre = g_o @ Wo + bo + x (residual). grid (4, 24)
// ---------------------------------------------------------------------------
__global__ void __launch_bounds__(256) outproj_kernel(
    const float* __restrict__ x, const float* __restrict__ Wo,
    const float* __restrict__ bo)
{
    gemm128_body(g_o, Wo, bo, x, g_pre, 1.0f, blockIdx.x, blockIdx.y);
}

// ---------------------------------------------------------------------------
// Kernel 5: LayerNorm rows of g_pre -> out. One block per row.
// ---------------------------------------------------------------------------
__global__ void __launch_bounds__(256) ln_kernel(
    const float* __restrict__ gamma, const float* __restrict__ beta,
    float* __restrict__ out)
{
    __shared__ float r1[8];
    __shared__ float bc;

    const int row = blockIdx.x;
    const int tid = threadIdx.x;
    const int lane = tid & 31, wid = tid >> 5;
    const float* pr = g_pre + (size_t)row * DD;

    float v0 = pr[tid], v1 = pr[tid + 256];
    float s = v0 + v1;
#pragma unroll
    for (int o = 16; o > 0; o >>= 1) s += __shfl_xor_sync(0xffffffffu, s, o);
    if (lane == 0) r1[wid] = s;
    __syncthreads();
    if (tid == 0) {
        float a = 0.0f;
#pragma unroll
        for (int w = 0; w < 8; w++) a += r1[w];
        bc = a * (1.0f / (float)DD);
    }
    __syncthreads();
    float mu = bc;

    float d0 = v0 - mu, d1 = v1 - mu;
    float q = d0 * d0 + d1 * d1;
#pragma unroll
    for (int o = 16; o > 0; o >>= 1) q += __shfl_xor_sync(0xffffffffu, q, o);
    if (lane == 0) r1[wid] = q;
    __syncthreads();
    if (tid == 0) {
        float a = 0.0f;
#pragma unroll
        for (int w = 0; w < 8; w++) a += r1[w];
        float var = a * (1.0f / (float)DD);
        bc = 1.0f / sqrtf(var + 1e-6f);
    }
    __syncthreads();
    float inv = bc;

    out[(size_t)row * DD + tid]       = d0 * inv * gamma[tid] + beta[tid];
    out[(size_t)row * DD + tid + 256] = d1 * inv * gamma[tid + 256] + beta[tid + 256];
}

// ---------------------------------------------------------------------------
// kernel_launch: inputs in metadata order:
// x, Wq, bq, Wk, bk, Wv, bv, Wo, bo, gamma, beta
// output: [ out (S*D) | attn (H*S*S) ] fp32
// ---------------------------------------------------------------------------
extern "C" void kernel_launch(void* const* d_in, const int* in_sizes, int n_in,
                              void* d_out, int out_size)
{
    const float* x     = (const float*)d_in[0];
    const float* Wq    = (const float*)d_in[1];
    const float* bq    = (const float*)d_in[2];
    const float* Wk    = (const float*)d_in[3];
    const float* bk    = (const float*)d_in[4];
    const float* Wv    = (const float*)d_in[5];
    const float* bv    = (const float*)d_in[6];
    const float* Wo    = (const float*)d_in[7];
    const float* bo    = (const float*)d_in[8];
    const float* gamma = (const float*)d_in[9];
    const float* beta  = (const float*)d_in[10];

    float* out  = (float*)d_out;
    float* attn = out + (size_t)SQ * DD;

    // allow >48KB dynamic smem for the fused kernel (idempotent; not a stream op)
    cudaFuncSetAttribute(entmax_av_kernel,
                         cudaFuncAttributeMaxDynamicSharedMemorySize, SMEM_FUSED);

    // 1. QKV projections (q pre-scaled by 1/8)
    qkv_kernel<<<dim3(4, 24, 3), 256>>>(x, Wq, bq, Wk, bk, Wv, bv);
    // 2. logits per head -> attn region
    qk_kernel<<<dim3(24, 24, 8), 256>>>(attn);
    // 3. fused entmax-1.5 + attn @ v -> attn (probs) and g_o
    entmax_av_kernel<<<dim3(SQ / RPC, HH), 256, SMEM_FUSED>>>(attn);
    // 4. out projection + residual -> g_pre
    outproj_kernel<<<dim3(4, 24), 256>>>(x, Wo, bo);
    // 5. LayerNorm -> out
    ln_kernel<<<SQ, 256>>>(gamma, beta, out);
}

// round 9
// speedup vs baseline: 1.0699x; 1.0699x over previous
#include <cuda_runtime.h>
#include <math.h>

// Problem constants
#define SQ  3072   // sequence length
#define DD  512    // model dim = H*DK = H*DV
#define HH  8      // heads
#define DKV 64     // head dim

#define RPC 16                         // query rows per fused CTA
#define PSTRIDE 3076                   // padded P row stride (floats); mod 32 = 4
#define SMEM_FUSED (RPC * PSTRIDE * 4 + 64 * 64 * 4)   // 196864 + 16384 = 213248

typedef unsigned long long ull;

// Scratch (device globals; no allocation allowed)
__device__ float g_q[SQ * DD];
__device__ float g_k[SQ * DD];
__device__ float g_v[SQ * DD];
__device__ float g_o[SQ * DD];
__device__ float g_pre[SQ * DD];

// ---------------------------------------------------------------------------
// Packed fp32x2 FMA (Blackwell sm_10x; 2 FMAs per instruction on fma pipe)
// ---------------------------------------------------------------------------
__device__ __forceinline__ void fma2(ull& d, ull a, ull b) {
    asm("fma.rn.f32x2 %0, %1, %2, %0;" : "+l"(d) : "l"(a), "l"(b));
}

__device__ __forceinline__ ull dup2(float v) {
    union { float2 f; ull u; } c;
    c.f = make_float2(v, v);
    return c.u;
}

// ---------------------------------------------------------------------------
// Shared-tile consumer: BK=16, 4 row-pairs per thread, 2*NJP columns/thread.
// Ast: k-major [16][132] floats; thread's rows = ty*8..ty*8+7.
// Bsd: ulonglong2 entries [16][NJP][17]; entry (k,jp,tx) holds duplicated
//      pairs (b,b) for columns tx*2NJP + 2jp and tx*2NJP + 2jp + 1.
// ---------------------------------------------------------------------------
template<int NJP>
__device__ __forceinline__ void consume16(const float* __restrict__ Ast,
                                          const ulonglong2* __restrict__ Bsd,
                                          ull accp[4][2 * NJP], int ty, int tx)
{
#pragma unroll
    for (int kk = 0; kk < 16; kk++) {
        ulonglong2 u0 = *(const ulonglong2*)(Ast + kk * 132 + ty * 8);
        ulonglong2 u1 = *(const ulonglong2*)(Ast + kk * 132 + ty * 8 + 4);
        ull ap0 = u0.x, ap1 = u0.y, ap2 = u1.x, ap3 = u1.y;
        const ulonglong2* bp = Bsd + kk * NJP * 17 + tx;
#pragma unroll
        for (int jp = 0; jp < NJP; jp++) {
            ulonglong2 bb = bp[jp * 17];
            fma2(accp[0][2 * jp], ap0, bb.x);
            fma2(accp[1][2 * jp], ap1, bb.x);
            fma2(accp[2][2 * jp], ap2, bb.x);
            fma2(accp[3][2 * jp], ap3, bb.x);
            fma2(accp[0][2 * jp + 1], ap0, bb.y);
            fma2(accp[1][2 * jp + 1], ap1, bb.y);
            fma2(accp[2][2 * jp + 1], ap2, bb.y);
            fma2(accp[3][2 * jp + 1], ap3, bb.y);
        }
    }
}

// ---------------------------------------------------------------------------
// 128x64-tile GEMM: C = (A@B + bias)*scale (+ resid). K=512, N=512 fixed.
// 128x64 tile (accp[4][4] = 32 regs) so 3 CTAs fit per SM -> latency hiding.
// Software-pipelined global->smem staging.
// ---------------------------------------------------------------------------
__device__ __forceinline__ void gemm64_body(
    const float* __restrict__ A, const float* __restrict__ B,
    const float* __restrict__ bias, const float* __restrict__ resid,
    float* __restrict__ C, float scale, int bx, int by)
{
    __shared__ __align__(16) float Ast[16 * 132];
    __shared__ __align__(16) ulonglong2 Bsd[16 * 2 * 17];

    const int tid = threadIdx.x;
    const int ty = tid >> 4, tx = tid & 15;
    const int arow = tid >> 1, acol = (tid & 1) * 8;
    const int brow = tid >> 4, bcol = tid & 15;

    ull accp[4][4];
#pragma unroll
    for (int i = 0; i < 4; i++)
#pragma unroll
        for (int j = 0; j < 4; j++) accp[i][j] = 0ull;

    const float* Ap = A + (size_t)(by * 128 + arow) * 512 + acol;
    const float* Bp = B + (size_t)brow * 512 + bx * 64 + bcol * 4;

    float4 a0 = *(const float4*)(Ap);
    float4 a1 = *(const float4*)(Ap + 4);
    float4 b0 = *(const float4*)(Bp);

    for (int k0 = 0; k0 < 512; k0 += 16) {
        Ast[(acol + 0) * 132 + arow] = a0.x;
        Ast[(acol + 1) * 132 + arow] = a0.y;
        Ast[(acol + 2) * 132 + arow] = a0.z;
        Ast[(acol + 3) * 132 + arow] = a0.w;
        Ast[(acol + 4) * 132 + arow] = a1.x;
        Ast[(acol + 5) * 132 + arow] = a1.y;
        Ast[(acol + 6) * 132 + arow] = a1.z;
        Ast[(acol + 7) * 132 + arow] = a1.w;
        Bsd[(brow * 2 + 0) * 17 + bcol] = make_ulonglong2(dup2(b0.x), dup2(b0.y));
        Bsd[(brow * 2 + 1) * 17 + bcol] = make_ulonglong2(dup2(b0.z), dup2(b0.w));
        __syncthreads();
        if (k0 + 16 < 512) {           // prefetch next chunk during consume
            a0 = *(const float4*)(Ap + k0 + 16);
            a1 = *(const float4*)(Ap + k0 + 20);
            b0 = *(const float4*)(Bp + (size_t)(k0 + 16) * 512);
        }
        consume16<2>(Ast, Bsd, accp, ty, tx);
        __syncthreads();
    }

#pragma unroll
    for (int ip = 0; ip < 4; ip++) {
        float2 f[4];
#pragma unroll
        for (int j = 0; j < 4; j++) f[j] = *(float2*)&accp[ip][j];
#pragma unroll
        for (int l = 0; l < 2; l++) {
            size_t row = (size_t)(by * 128 + ty * 8 + ip * 2 + l);
            int col = bx * 64 + tx * 4;
            float4 r;
            r.x = ((l ? f[0].y : f[0].x) + bias[col + 0]) * scale;
            r.y = ((l ? f[1].y : f[1].x) + bias[col + 1]) * scale;
            r.z = ((l ? f[2].y : f[2].x) + bias[col + 2]) * scale;
            r.w = ((l ? f[3].y : f[3].x) + bias[col + 3]) * scale;
            if (resid) {
                float4 e = *(const float4*)(resid + row * 512 + col);
                r.x += e.x; r.y += e.y; r.z += e.z; r.w += e.w;
            }
            *(float4*)(C + row * 512 + col) = r;
        }
    }
}

// ---------------------------------------------------------------------------
// Kernel 1: QKV projections. grid (8, 24, 3), 256 threads
// ---------------------------------------------------------------------------
__global__ void __launch_bounds__(256, 3) qkv_kernel(
    const float* __restrict__ x,
    const float* __restrict__ Wq, const float* __restrict__ bq,
    const float* __restrict__ Wk, const float* __restrict__ bk,
    const float* __restrict__ Wv, const float* __restrict__ bv)
{
    const int z = blockIdx.z;
    const float* B    = (z == 0) ? Wq : ((z == 1) ? Wk : Wv);
    const float* bias = (z == 0) ? bq : ((z == 1) ? bk : bv);
    float* C          = (z == 0) ? g_q : ((z == 1) ? g_k : g_v);
    const float scale = (z == 0) ? 0.125f : 1.0f;   // 1/sqrt(64)
    gemm64_body(x, B, bias, nullptr, C, scale, blockIdx.x, blockIdx.y);
}

// ---------------------------------------------------------------------------
// Kernel 2: logits[h] = q_h @ k_h^T. Tile 128 q-rows x 64 k-rows, K=64
// (4 chunks of 16 d). grid (48, 24, 8), 256 threads.
// K loader: thread owns key row j = tid&63, d-quad dq = (tid>>6)*4.
// Entry (d, jp, txj) with txj=j>>2, jp=(j&3)>>1, half=j&1 (consumer column
// txj*4 + 2jp + half = j). Software-pipelined.
// ---------------------------------------------------------------------------
__global__ void __launch_bounds__(256, 3) qk_kernel(float* __restrict__ attn)
{
    const int h = blockIdx.z;
    const int bx = blockIdx.x, by = blockIdx.y;
    __shared__ __align__(16) float Qst[16 * 132];
    __shared__ __align__(16) ulonglong2 Ksd[16 * 2 * 17];

    const int tid = threadIdx.x;
    const int ty = tid >> 4, tx = tid & 15;
    const int arow = tid >> 1, acol = (tid & 1) * 8;   // Q loader
    const int j = tid & 63, dq = (tid >> 6) * 4;       // K loader

    ull accp[4][4];
#pragma unroll
    for (int i = 0; i < 4; i++)
#pragma unroll
        for (int q = 0; q < 4; q++) accp[i][q] = 0ull;

    const float* qp = g_q + (size_t)(by * 128 + arow) * DD + h * 64 + acol;
    const float* kp = g_k + (size_t)(bx * 64 + j) * DD + h * 64 + dq;
    ull* kd = (ull*)Ksd;
    const int txj = j >> 2, jp = (j & 3) >> 1, half = j & 1;

    float4 q0 = *(const float4*)(qp);
    float4 q1 = *(const float4*)(qp + 4);
    float4 k0 = *(const float4*)(kp);

#pragma unroll
    for (int c = 0; c < 4; c++) {
        Qst[(acol + 0) * 132 + arow] = q0.x;
        Qst[(acol + 1) * 132 + arow] = q0.y;
        Qst[(acol + 2) * 132 + arow] = q0.z;
        Qst[(acol + 3) * 132 + arow] = q0.w;
        Qst[(acol + 4) * 132 + arow] = q1.x;
        Qst[(acol + 5) * 132 + arow] = q1.y;
        Qst[(acol + 6) * 132 + arow] = q1.z;
        Qst[(acol + 7) * 132 + arow] = q1.w;
        kd[(((dq + 0) * 2 + jp) * 17 + txj) * 2 + half] = dup2(k0.x);
        kd[(((dq + 1) * 2 + jp) * 17 + txj) * 2 + half] = dup2(k0.y);
        kd[(((dq + 2) * 2 + jp) * 17 + txj) * 2 + half] = dup2(k0.z);
        kd[(((dq + 3) * 2 + jp) * 17 + txj) * 2 + half] = dup2(k0.w);
        __syncthreads();
        if (c < 3) {                   // prefetch next chunk during consume
            q0 = *(const float4*)(qp + (c + 1) * 16);
            q1 = *(const float4*)(qp + (c + 1) * 16 + 4);
            k0 = *(const float4*)(kp + (c + 1) * 16);
        }
        consume16<2>(Qst, Ksd, accp, ty, tx);
        __syncthreads();
    }

    float* dst = attn + (size_t)h * SQ * SQ;
#pragma unroll
    for (int ip = 0; ip < 4; ip++) {
        float2 f[4];
#pragma unroll
        for (int q = 0; q < 4; q++) f[q] = *(float2*)&accp[ip][q];
#pragma unroll
        for (int l = 0; l < 2; l++) {
            size_t row = (size_t)(by * 128 + ty * 8 + ip * 2 + l);
            int col = bx * 64 + tx * 4;
            float4 r;
            r.x = l ? f[0].y : f[0].x;
            r.y = l ? f[1].y : f[1].x;
            r.z = l ? f[2].y : f[2].x;
            r.w = l ? f[3].y : f[3].x;
            *(float4*)(dst + row * SQ + col) = r;
        }
    }
}

// ---------------------------------------------------------------------------
// Kernel 3 (FUSED): entmax-1.5 + (attn @ v) for a 16-row x 1-head tile.
// grid (192, 8), 512 threads (16 warps = 4/SMSP), 213248 B dynamic smem.
//
// Phase 1: stage logits tile [16][3072] into smem P (PSTRIDE pad).
// Phase 2: ONE warp per row. Single merged pass computes max/sum/sumsq of raw
//          logits (shift identities recover the stats of x=(v-m)/2), then the
//          closed-form full-support tau init and 8 Newton iterations
//          (monotone from below). Finalize writes p to global + smem.
// Phase 3: o[16][64] = P @ V_head. Thread = (co: 8-col group of 8,
//          rp: row-pair of 8, ks: 8-way k-split, ks = tid>>6 warp-uniform).
//          V streamed in 64-row (16 KB) chunks, register-prefetched.
//          Cross-ks reduction: 3 log-rounds via the V buffer
//          (hlf=4 round: 256 threads x 8 ull = 2048 ull = exact fit).
// ---------------------------------------------------------------------------
__global__ void __launch_bounds__(512) entmax_av_kernel(float* __restrict__ attn)
{
    extern __shared__ __align__(16) char sm_[];
    float* P  = (float*)sm_;                 // [RPC][PSTRIDE]
    float* Vs = P + RPC * PSTRIDE;           // [64][64]
    ull*   scratch = (ull*)Vs;               // 2048 ull, reused after AV loop

    const int tid = threadIdx.x;
    const int h = blockIdx.y;
    const int row0 = blockIdx.x * RPC;

    float* gP = attn + (size_t)h * SQ * SQ + (size_t)row0 * SQ; // 16*3072 contiguous

    // ---- Phase 1: stage logits tile ----
    {
        const float4* src = (const float4*)gP;
#pragma unroll
        for (int j = 0; j < 24; j++) {
            int f4 = tid + j * 512;          // 0..12287
            int row = f4 / 768;              // 768 float4 per row
            int k4  = f4 - row * 768;
            *(float4*)(P + row * PSTRIDE + k4 * 4) = src[f4];
        }
    }
    __syncthreads();

    // ---- Phase 2: entmax (one warp per row) ----
    const int r    = tid >> 5;     // row 0..15
    const int lane = tid & 31;
    const float4* rowp = (const float4*)(P + r * PSTRIDE);

    // merged pass: max, sum, sumsq of raw logits v
    float m = -1e30f, s1 = 0.0f, s2 = 0.0f;
#pragma unroll
    for (int j = 0; j < 24; j++) {
        float4 v = rowp[lane + 32 * j];
        m = fmaxf(m, fmaxf(fmaxf(v.x, v.y), fmaxf(v.z, v.w)));
        s1 += (v.x + v.y) + (v.z + v.w);
        s2 = fmaf(v.x, v.x, s2); s2 = fmaf(v.y, v.y, s2);
        s2 = fmaf(v.z, v.z, s2); s2 = fmaf(v.w, v.w, s2);
    }
#pragma unroll
    for (int o = 16; o > 0; o >>= 1) {
        m  = fmaxf(m, __shfl_xor_sync(0xffffffffu, m, o));
        s1 += __shfl_xor_sync(0xffffffffu, s1, o);
        s2 += __shfl_xor_sync(0xffffffffu, s2, o);
    }
    // stats of x = (v - m)/2:  sum_x = (s1 - n m)/2, sumsq_x = (s2 - 2m s1 + n m^2)/4
    const float n = (float)SQ, invn = 1.0f / (float)SQ;
    float sum_x   = 0.5f * (s1 - n * m);
    float sumsq_x = 0.25f * (s2 - 2.0f * m * s1 + n * m * m);
    float mean = sum_x * invn;
    float var  = sumsq_x * invn - mean * mean;
    float delta = fmaxf((1.0f - n * var) * invn, 0.0f);
    float tau = fminf(mean - sqrtf(delta), -1e-12f);

    // 8 Newton iterations (monotone from below; all lanes of a row agree)
#pragma unroll
    for (int it = 0; it < 8; it++) {
        float cc = 0.5f * m + tau;    // u = 0.5*v - cc
        float a = 0.0f, b = 0.0f;
#pragma unroll
        for (int j = 0; j < 24; j++) {
            float4 v = rowp[lane + 32 * j];
            float u0 = fmaxf(fmaf(0.5f, v.x, -cc), 0.0f);
            float u1 = fmaxf(fmaf(0.5f, v.y, -cc), 0.0f);
            float u2 = fmaxf(fmaf(0.5f, v.z, -cc), 0.0f);
            float u3 = fmaxf(fmaf(0.5f, v.w, -cc), 0.0f);
            a += (u0 + u1) + (u2 + u3);
            b = fmaf(u0, u0, b); b = fmaf(u1, u1, b);
            b = fmaf(u2, u2, b); b = fmaf(u3, u3, b);
        }
#pragma unroll
        for (int o = 16; o > 0; o >>= 1) {
            a += __shfl_xor_sync(0xffffffffu, a, o);
            b += __shfl_xor_sync(0xffffffffu, b, o);
        }
        if (a > 0.0f) tau += (b - 1.0f) / (2.0f * a);
    }

    // finalize p, write to global AND back to smem
    {
        float cc = 0.5f * m + tau;
        float4* wsm = (float4*)(P + r * PSTRIDE);
        float4* wgl = (float4*)(gP + (size_t)r * SQ);
#pragma unroll
        for (int j = 0; j < 24; j++) {
            float4 v = wsm[lane + 32 * j];
            float4 p;
            float u;
            u = fmaxf(fmaf(0.5f, v.x, -cc), 0.0f); p.x = u * u;
            u = fmaxf(fmaf(0.5f, v.y, -cc), 0.0f); p.y = u * u;
            u = fmaxf(fmaf(0.5f, v.z, -cc), 0.0f); p.z = u * u;
            u = fmaxf(fmaf(0.5f, v.w, -cc), 0.0f); p.w = u * u;
            wsm[lane + 32 * j] = p;
            wgl[lane + 32 * j] = p;
        }
    }
    __syncthreads();

    // ---- Phase 3: AV from smem (V register-prefetched one chunk ahead) ----
    const int co = tid & 7;           // 8-col group
    const int rp = (tid >> 3) & 7;    // row pair
    const int ks = tid >> 6;          // 0..7 (uniform per 2 warps)

    ull acc[2][4];
#pragma unroll
    for (int l = 0; l < 2; l++)
#pragma unroll
        for (int q = 0; q < 4; q++) acc[l][q] = 0ull;

    const float* p0base = P + (2 * rp) * PSTRIDE;
    const float* p1base = P + (2 * rp + 1) * PSTRIDE;

    const int vkr = tid >> 4;               // 0..31: V row within half-chunk
    const int vc4 = (tid & 15) * 4;         // V col
    const float* vsrc = g_v + (size_t)vkr * DD + h * 64 + vc4;

    float4 vreg[2];
#pragma unroll
    for (int j = 0; j < 2; j++)
        vreg[j] = *(const float4*)(vsrc + (size_t)(j * 32) * DD);

    for (int kc = 0; kc < SQ; kc += 64) {
        // publish current chunk [64][64]
#pragma unroll
        for (int j = 0; j < 2; j++)
            *(float4*)(Vs + (j * 32 + vkr) * 64 + vc4) = vreg[j];
        __syncthreads();
        if (kc + 64 < SQ) {           // prefetch next chunk during compute
#pragma unroll
            for (int j = 0; j < 2; j++)
                vreg[j] = *(const float4*)(vsrc + (size_t)(kc + 64 + j * 32) * DD);
        }
#pragma unroll
        for (int kk = 0; kk < 8; kk++) {
            int kl = ks * 8 + kk;            // 0..63
            float p0 = p0base[kc + kl];
            float p1 = p1base[kc + kl];
            ull a0 = dup2(p0), a1 = dup2(p1);
            const ulonglong2* vv = (const ulonglong2*)(Vs + kl * 64 + co * 8);
#pragma unroll
            for (int q2 = 0; q2 < 2; q2++) {
                ulonglong2 b = vv[q2];
                fma2(acc[0][2 * q2],     a0, b.x);
                fma2(acc[1][2 * q2],     a1, b.x);
                fma2(acc[0][2 * q2 + 1], a0, b.y);
                fma2(acc[1][2 * q2 + 1], a1, b.y);
            }
        }
        __syncthreads();
    }

    // cross-ks reduction (3 log-rounds, reusing Vs as scratch)
    for (int hlf = 4; hlf >= 1; hlf >>= 1) {
        if (ks >= hlf && ks < 2 * hlf) {
            ull* d = scratch + (size_t)(tid - hlf * 64) * 8;
#pragma unroll
            for (int q = 0; q < 4; q++) { d[q] = acc[0][q]; d[q + 4] = acc[1][q]; }
        }
        __syncthreads();
        if (ks < hlf) {
            const ull* s = scratch + (size_t)tid * 8;
#pragma unroll
            for (int q = 0; q < 4; q++) {
                float2 f0 = *(float2*)&acc[0][q];
                float2 g0 = *(const float2*)&s[q];
                f0.x += g0.x; f0.y += g0.y;
                acc[0][q] = *(ull*)&f0;
                float2 f1 = *(float2*)&acc[1][q];
                float2 g1 = *(const float2*)&s[q + 4];
                f1.x += g1.x; f1.y += g1.y;
                acc[1][q] = *(ull*)&f1;
            }
        }
        __syncthreads();
    }

    // write o tile (threads with ks == 0, i.e. tid < 64)
    if (tid < 64) {
#pragma unroll
        for (int l = 0; l < 2; l++) {
            size_t row = (size_t)(row0 + 2 * rp + l);
            float* op = g_o + row * DD + h * 64 + co * 8;
            float2 e0 = *(float2*)&acc[l][0];
            float2 e1 = *(float2*)&acc[l][1];
            float2 e2 = *(float2*)&acc[l][2];
            float2 e3 = *(float2*)&acc[l][3];
            float4 w0, w1;
            w0.x = e0.x; w0.y = e0.y; w0.z = e1.x; w0.w = e1.y;
            w1.x = e2.x; w1.y = e2.y; w1.z = e3.x; w1.w = e3.y;
            *(float4*)(op)     = w0;
            *(float4*)(op + 4) = w1;
        }
    }
}

// ---------------------------------------------------------------------------
// Kernel 4: pre = g_o @ Wo + bo + x (residual). grid (8, 24)
// ---------------------------------------------------------------------------
__global__ void __launch_bounds__(256, 3) outproj_kernel(
    const float* __restrict__ x, const float* __restrict__ Wo,
    const float* __restrict__ bo)
{
    gemm64_body(g_o, Wo, bo, x, g_pre, 1.0f, blockIdx.x, blockIdx.y);
}

// ---------------------------------------------------------------------------
// Kernel 5: LayerNorm rows of g_pre -> out. One block per row.
// ---------------------------------------------------------------------------
__global__ void __launch_bounds__(256) ln_kernel(
    const float* __restrict__ gamma, const float* __restrict__ beta,
    float* __restrict__ out)
{
    __shared__ float r1[8];
    __shared__ float bc;

    const int row = blockIdx.x;
    const int tid = threadIdx.x;
    const int lane = tid & 31, wid = tid >> 5;
    const float* pr = g_pre + (size_t)row * DD;

    float v0 = pr[tid], v1 = pr[tid + 256];
    float s = v0 + v1;
#pragma unroll
    for (int o = 16; o > 0; o >>= 1) s += __shfl_xor_sync(0xffffffffu, s, o);
    if (lane == 0) r1[wid] = s;
    __syncthreads();
    if (tid == 0) {
        float a = 0.0f;
#pragma unroll
        for (int w = 0; w < 8; w++) a += r1[w];
        bc = a * (1.0f / (float)DD);
    }
    __syncthreads();
    float mu = bc;

    float d0 = v0 - mu, d1 = v1 - mu;
    float q = d0 * d0 + d1 * d1;
#pragma unroll
    for (int o = 16; o > 0; o >>= 1) q += __shfl_xor_sync(0xffffffffu, q, o);
    if (lane == 0) r1[wid] = q;
    __syncthreads();
    if (tid == 0) {
        float a = 0.0f;
#pragma unroll
        for (int w = 0; w < 8; w++) a += r1[w];
        float var = a * (1.0f / (float)DD);
        bc = 1.0f / sqrtf(var + 1e-6f);
    }
    __syncthreads();
    float inv = bc;

    out[(size_t)row * DD + tid]       = d0 * inv * gamma[tid] + beta[tid];
    out[(size_t)row * DD + tid + 256] = d1 * inv * gamma[tid + 256] + beta[tid + 256];
}

// ---------------------------------------------------------------------------
// kernel_launch: inputs in metadata order:
// x, Wq, bq, Wk, bk, Wv, bv, Wo, bo, gamma, beta
// output: [ out (S*D) | attn (H*S*S) ] fp32
// ---------------------------------------------------------------------------
extern "C" void kernel_launch(void* const* d_in, const int* in_sizes, int n_in,
                              void* d_out, int out_size)
{
    const float* x     = (const float*)d_in[0];
    const float* Wq    = (const float*)d_in[1];
    const float* bq    = (const float*)d_in[2];
    const float* Wk    = (const float*)d_in[3];
    const float* bk    = (const float*)d_in[4];
    const float* Wv    = (const float*)d_in[5];
    const float* bv    = (const float*)d_in[6];
    const float* Wo    = (const float*)d_in[7];
    const float* bo    = (const float*)d_in[8];
    const float* gamma = (const float*)d_in[9];
    const float* beta  = (const float*)d_in[10];

    float* out  = (float*)d_out;
    float* attn = out + (size_t)SQ * DD;

    // allow >48KB dynamic smem for the fused kernel (idempotent; not a stream op)
    cudaFuncSetAttribute(entmax_av_kernel,
                         cudaFuncAttributeMaxDynamicSharedMemorySize, SMEM_FUSED);

    // 1. QKV projections (q pre-scaled by 1/8)
    qkv_kernel<<<dim3(8, 24, 3), 256>>>(x, Wq, bq, Wk, bk, Wv, bv);
    // 2. logits per head -> attn region
    qk_kernel<<<dim3(48, 24, 8), 256>>>(attn);
    // 3. fused entmax-1.5 + attn @ v -> attn (probs) and g_o
    entmax_av_kernel<<<dim3(SQ / RPC, HH), 512, SMEM_FUSED>>>(attn);
    // 4. out projection + residual -> g_pre
    outproj_kernel<<<dim3(8, 24), 256>>>(x, Wo, bo);
    // 5. LayerNorm -> out
    ln_kernel<<<SQ, 256>>>(gamma, beta, out);
}